// round 2
// baseline (speedup 1.0000x reference)
#include <cuda_runtime.h>
#include <math.h>

#define NEARV     2.0f
#define FARV      6.0f
#define FAR_DIST  1e10f
#define S         128
#define RPB       8            // rays per block (8 warps)
#define MAX_BLK   16384

// Deterministic scratch for the scalar reduction (no allocations allowed).
__device__ float g_partials[MAX_BLK];

__global__ __launch_bounds__(256) void integrate_kernel(
    const float* __restrict__ raw,     // [N, S, 4]
    const float* __restrict__ zvals,   // [N, S]
    const float* __restrict__ rays_d,  // [N, 3]
    float* __restrict__ out,           // [3N chs | N depth | 1 scalar]
    int N)
{
    __shared__ float sh_raw[RPB][S * 4];   // 16 KB
    __shared__ float sh_z[RPB][S];         // 4 KB
    __shared__ float sh_ent[RPB];

    const int warp = threadIdx.x >> 5;
    const int lane = threadIdx.x & 31;
    const int ray  = blockIdx.x * RPB + warp;
    const bool active = (ray < N);

    // ---- coalesced stage-in: warp loads its own ray ----
    if (active) {
        const float4* rp = (const float4*)(raw + (size_t)ray * (S * 4));
        float4* sp = (float4*)sh_raw[warp];
        #pragma unroll
        for (int k = 0; k < S / 32; k++)           // 128 float4s, 4 per lane
            sp[lane + 32 * k] = rp[lane + 32 * k];
        const float4* zp = (const float4*)(zvals + (size_t)ray * S);
        ((float4*)sh_z[warp])[lane] = zp[lane];    // 32 float4s, 1 per lane
    }
    __syncwarp();

    float ent = 0.0f;
    if (active) {
        // ray direction norm (broadcast load, L1 hit)
        const float* rd = rays_d + (size_t)ray * 3;
        const float nrm = sqrtf(rd[0] * rd[0] + rd[1] * rd[1] + rd[2] * rd[2]);

        // each lane owns samples [4*lane, 4*lane+3]
        const int j0 = 4 * lane;
        float a[4], t[4], zn[4];
        float prod = 1.0f;
        #pragma unroll
        for (int k = 0; k < 4; k++) {
            const int j = j0 + k;
            const float z = sh_z[warp][j];
            float dist = (j < S - 1) ? (sh_z[warp][j + 1] - z) : FAR_DIST;
            dist *= nrm;
            const float sigma = sh_raw[warp][j * 4 + 3];
            const float alpha = 1.0f - expf(-fmaxf(sigma, 0.0f) * dist);
            a[k]  = alpha;
            t[k]  = 1.0f - alpha + 1e-10f;
            zn[k] = (FARV - z) * (1.0f / (FARV - NEARV));
            prod *= t[k];
        }

        // multiplicative exclusive warp scan of per-lane products
        float scan = prod;
        #pragma unroll
        for (int off = 1; off < 32; off <<= 1) {
            const float v = __shfl_up_sync(0xffffffffu, scan, off);
            if (lane >= off) scan *= v;
        }
        float excl = __shfl_up_sync(0xffffffffu, scan, 1);
        if (lane == 0) excl = 1.0f;

        // weights, accumulators
        float c0 = 0.f, c1 = 0.f, c2 = 0.f, dn = 0.f, ws = 0.f;
        const float invD = 1.0f / (1.0f + 1e-6f);
        float tr = excl;
        #pragma unroll
        for (int k = 0; k < 4; k++) {
            const int j = j0 + k;
            const float w = a[k] * tr;
            c0 += w * sh_raw[warp][j * 4 + 0];
            c1 += w * sh_raw[warp][j * 4 + 1];
            c2 += w * sh_raw[warp][j * 4 + 2];
            dn += w * zn[k];
            ws += w;
            const float p = w * invD;
            if (p > 0.0f) ent += p * logf(p);
            tr *= t[k];
        }

        // warp reductions
        #pragma unroll
        for (int off = 16; off > 0; off >>= 1) {
            c0  += __shfl_down_sync(0xffffffffu, c0,  off);
            c1  += __shfl_down_sync(0xffffffffu, c1,  off);
            c2  += __shfl_down_sync(0xffffffffu, c2,  off);
            dn  += __shfl_down_sync(0xffffffffu, dn,  off);
            ws  += __shfl_down_sync(0xffffffffu, ws,  off);
            ent += __shfl_down_sync(0xffffffffu, ent, off);
        }

        if (lane == 0) {
            out[(size_t)ray * 3 + 0] = c0;
            out[(size_t)ray * 3 + 1] = c1;
            out[(size_t)ray * 3 + 2] = c2;
            out[(size_t)3 * N + ray] = dn / (ws + 1e-5f);
            const float p_last = (1.0f - ws + 1e-6f) * invD;
            if (p_last > 0.0f) ent += p_last * logf(p_last);
            sh_ent[warp] = ent;
        }
    } else if (lane == 0) {
        sh_ent[warp] = 0.0f;
    }

    __syncthreads();
    if (threadIdx.x == 0) {
        float s = 0.0f;
        #pragma unroll
        for (int w = 0; w < RPB; w++) s += sh_ent[w];
        g_partials[blockIdx.x] = s;
    }
}

__global__ __launch_bounds__(256) void reduce_kernel(float* __restrict__ out,
                                                     int nblocks, int N)
{
    __shared__ double sh[256];
    double s = 0.0;
    for (int i = threadIdx.x; i < nblocks; i += 256)
        s += (double)g_partials[i];
    sh[threadIdx.x] = s;
    __syncthreads();
    for (int off = 128; off > 0; off >>= 1) {
        if (threadIdx.x < off) sh[threadIdx.x] += sh[threadIdx.x + off];
        __syncthreads();
    }
    if (threadIdx.x == 0)
        out[(size_t)4 * N] = (float)(-sh[0]);   // sparsity_loss = -sum(p log p)
}

extern "C" void kernel_launch(void* const* d_in, const int* in_sizes, int n_in,
                              void* d_out, int out_size)
{
    const float* raw    = (const float*)d_in[0];
    const float* zvals  = (const float*)d_in[1];
    const float* rays_d = (const float*)d_in[2];
    float* out = (float*)d_out;

    const int N = in_sizes[2] / 3;               // rays_d is [N,3]
    const int blocks = (N + RPB - 1) / RPB;

    integrate_kernel<<<blocks, 256>>>(raw, zvals, rays_d, out, N);
    reduce_kernel<<<1, 256>>>(out, blocks, N);
}

// round 3
// speedup vs baseline: 1.2439x; 1.2439x over previous
#include <cuda_runtime.h>
#include <math.h>

#define NEARV     2.0f
#define FARV      6.0f
#define FAR_DIST  1e10f
#define S         128
#define RPB       8            // rays per block (8 warps of 32 -> 256 threads)
#define MAX_BLK   16384

// Deterministic scratch for the fused scalar reduction (no allocations allowed).
__device__ float        g_partials[MAX_BLK];
__device__ unsigned int g_count = 0;

__global__ __launch_bounds__(256) void integrate_kernel(
    const float* __restrict__ raw,     // [N, S, 4]
    const float* __restrict__ zvals,   // [N, S]
    const float* __restrict__ rays_d,  // [N, 3]
    float* __restrict__ out,           // [3N chs | N depth | 1 scalar]
    int N)
{
    __shared__ float  sh_ent[RPB];
    __shared__ double sh_red[256];
    __shared__ bool   sh_last;

    const int warp = threadIdx.x >> 5;
    const int lane = threadIdx.x & 31;
    const int ray  = blockIdx.x * RPB + warp;

    float ent = 0.0f;
    if (ray < N) {
        // ---- direct, front-batched loads (5 independent LDG.128 / thread) ----
        const float4* rp = (const float4*)raw + (size_t)ray * S;   // sample j = float4 j
        const int j0 = 4 * lane;
        const float4 r0 = rp[j0 + 0];
        const float4 r1 = rp[j0 + 1];
        const float4 r2 = rp[j0 + 2];
        const float4 r3 = rp[j0 + 3];
        const float4 z4 = ((const float4*)zvals)[(size_t)ray * (S / 4) + lane];

        const float* rd = rays_d + (size_t)ray * 3;                // broadcast, L1
        const float nrm = sqrtf(rd[0] * rd[0] + rd[1] * rd[1] + rd[2] * rd[2]);

        // boundary z: next lane's first z (lane 31 uses FAR_DIST anyway)
        const float znext = __shfl_down_sync(0xffffffffu, z4.x, 1);

        float zz[4] = { z4.x, z4.y, z4.z, z4.w };
        float sg[4] = { r0.w, r1.w, r2.w, r3.w };
        float dist[4];
        dist[0] = (z4.y - z4.x) * nrm;
        dist[1] = (z4.z - z4.y) * nrm;
        dist[2] = (z4.w - z4.z) * nrm;
        dist[3] = (lane == 31) ? (FAR_DIST * nrm) : ((znext - z4.w) * nrm);

        float a[4], t[4];
        float prod = 1.0f;
        #pragma unroll
        for (int k = 0; k < 4; k++) {
            const float alpha = 1.0f - __expf(-fmaxf(sg[k], 0.0f) * dist[k]);
            a[k] = alpha;
            t[k] = 1.0f - alpha + 1e-10f;
            prod *= t[k];
        }

        // multiplicative exclusive warp scan of per-lane products
        float scan = prod;
        #pragma unroll
        for (int off = 1; off < 32; off <<= 1) {
            const float v = __shfl_up_sync(0xffffffffu, scan, off);
            if (lane >= off) scan *= v;
        }
        float tr = __shfl_up_sync(0xffffffffu, scan, 1);
        if (lane == 0) tr = 1.0f;

        // weights & accumulation (chs come straight from registers)
        const float invD = 1.0f / (1.0f + 1e-6f);
        float c0 = 0.f, c1 = 0.f, c2 = 0.f, dn = 0.f, ws = 0.f;
        const float4 rr[4] = { r0, r1, r2, r3 };
        #pragma unroll
        for (int k = 0; k < 4; k++) {
            const float w = a[k] * tr;
            c0 += w * rr[k].x;
            c1 += w * rr[k].y;
            c2 += w * rr[k].z;
            dn += w * (FARV - zz[k]) * (1.0f / (FARV - NEARV));
            ws += w;
            const float p = w * invD;
            if (p > 0.0f) ent += p * __logf(p);
            tr *= t[k];
        }

        // warp reductions
        #pragma unroll
        for (int off = 16; off > 0; off >>= 1) {
            c0  += __shfl_down_sync(0xffffffffu, c0,  off);
            c1  += __shfl_down_sync(0xffffffffu, c1,  off);
            c2  += __shfl_down_sync(0xffffffffu, c2,  off);
            dn  += __shfl_down_sync(0xffffffffu, dn,  off);
            ws  += __shfl_down_sync(0xffffffffu, ws,  off);
            ent += __shfl_down_sync(0xffffffffu, ent, off);
        }

        if (lane == 0) {
            out[(size_t)ray * 3 + 0] = c0;
            out[(size_t)ray * 3 + 1] = c1;
            out[(size_t)ray * 3 + 2] = c2;
            out[(size_t)3 * N + ray] = dn / (ws + 1e-5f);
            const float p_last = (1.0f - ws + 1e-6f) * invD;
            if (p_last > 0.0f) ent += p_last * __logf(p_last);
            sh_ent[warp] = ent;
        }
    } else if (lane == 0) {
        sh_ent[warp] = 0.0f;
    }

    __syncthreads();

    // ---- fused deterministic grid reduction (threadfence-reduction pattern) ----
    if (threadIdx.x == 0) {
        float s = 0.0f;
        #pragma unroll
        for (int w = 0; w < RPB; w++) s += sh_ent[w];
        g_partials[blockIdx.x] = s;
        __threadfence();
        const unsigned int done = atomicAdd(&g_count, 1u);
        sh_last = (done == gridDim.x - 1);
    }
    __syncthreads();

    if (sh_last) {
        // last block: sum all partials in a fixed order -> deterministic
        double s = 0.0;
        for (int i = threadIdx.x; i < (int)gridDim.x; i += 256)
            s += (double)g_partials[i];
        sh_red[threadIdx.x] = s;
        __syncthreads();
        #pragma unroll
        for (int off = 128; off > 0; off >>= 1) {
            if (threadIdx.x < off) sh_red[threadIdx.x] += sh_red[threadIdx.x + off];
            __syncthreads();
        }
        if (threadIdx.x == 0) {
            out[(size_t)4 * N] = (float)(-sh_red[0]);   // sparsity_loss
            g_count = 0;                                 // re-arm for next replay
        }
    }
}

extern "C" void kernel_launch(void* const* d_in, const int* in_sizes, int n_in,
                              void* d_out, int out_size)
{
    const float* raw    = (const float*)d_in[0];
    const float* zvals  = (const float*)d_in[1];
    const float* rays_d = (const float*)d_in[2];
    float* out = (float*)d_out;

    const int N = in_sizes[2] / 3;               // rays_d is [N,3]
    const int blocks = (N + RPB - 1) / RPB;

    integrate_kernel<<<blocks, 256>>>(raw, zvals, rays_d, out, N);
}

// round 4
// speedup vs baseline: 1.2504x; 1.0052x over previous
#include <cuda_runtime.h>
#include <math.h>

#define NEARV     2.0f
#define FARV      6.0f
#define FAR_DIST  1e10f
#define S         128
#define RPB       8            // rays per block (8 warps of 32 -> 256 threads)
#define MAX_BLK   16384

// Deterministic scratch for the fused scalar reduction (no allocations allowed).
__device__ float        g_partials[MAX_BLK];
__device__ unsigned int g_count = 0;

__global__ __launch_bounds__(256) void integrate_kernel(
    const float* __restrict__ raw,     // [N, S, 4]
    const float* __restrict__ zvals,   // [N, S]
    const float* __restrict__ rays_d,  // [N, 3]
    float* __restrict__ out,           // [3N chs | N depth | 1 scalar]
    int N)
{
    __shared__ float  sh_ent[RPB];
    __shared__ double sh_red[256];
    __shared__ bool   sh_last;

    const int warp = threadIdx.x >> 5;
    const int lane = threadIdx.x & 31;
    const int ray  = blockIdx.x * RPB + warp;

    float ent = 0.0f;
    if (ray < N) {
        // ---- direct, front-batched loads (5 independent LDG.128 / thread) ----
        const float4* rp = (const float4*)raw + (size_t)ray * S;   // sample j = float4 j
        const int j0 = 4 * lane;
        const float4 r0 = rp[j0 + 0];
        const float4 r1 = rp[j0 + 1];
        const float4 r2 = rp[j0 + 2];
        const float4 r3 = rp[j0 + 3];
        const float4 z4 = ((const float4*)zvals)[(size_t)ray * (S / 4) + lane];

        const float* rd = rays_d + (size_t)ray * 3;                // broadcast, L1
        const float nrm = sqrtf(rd[0] * rd[0] + rd[1] * rd[1] + rd[2] * rd[2]);

        // boundary z: next lane's first z (lane 31 uses FAR_DIST anyway)
        const float znext = __shfl_down_sync(0xffffffffu, z4.x, 1);

        float zz[4] = { z4.x, z4.y, z4.z, z4.w };
        float sg[4] = { r0.w, r1.w, r2.w, r3.w };
        float dist[4];
        dist[0] = (z4.y - z4.x) * nrm;
        dist[1] = (z4.z - z4.y) * nrm;
        dist[2] = (z4.w - z4.z) * nrm;
        dist[3] = (lane == 31) ? (FAR_DIST * nrm) : ((znext - z4.w) * nrm);

        float a[4], t[4];
        float prod = 1.0f;
        #pragma unroll
        for (int k = 0; k < 4; k++) {
            const float alpha = 1.0f - __expf(-fmaxf(sg[k], 0.0f) * dist[k]);
            a[k] = alpha;
            t[k] = 1.0f - alpha + 1e-10f;
            prod *= t[k];
        }

        // multiplicative exclusive warp scan of per-lane products
        float scan = prod;
        #pragma unroll
        for (int off = 1; off < 32; off <<= 1) {
            const float v = __shfl_up_sync(0xffffffffu, scan, off);
            if (lane >= off) scan *= v;
        }
        float tr = __shfl_up_sync(0xffffffffu, scan, 1);
        if (lane == 0) tr = 1.0f;

        // weights & accumulation (chs come straight from registers)
        const float invD = 1.0f / (1.0f + 1e-6f);
        float c0 = 0.f, c1 = 0.f, c2 = 0.f, dn = 0.f, ws = 0.f;
        const float4 rr[4] = { r0, r1, r2, r3 };
        #pragma unroll
        for (int k = 0; k < 4; k++) {
            const float w = a[k] * tr;
            c0 += w * rr[k].x;
            c1 += w * rr[k].y;
            c2 += w * rr[k].z;
            dn += w * (FARV - zz[k]) * (1.0f / (FARV - NEARV));
            ws += w;
            const float p = w * invD;
            if (p > 0.0f) ent += p * __logf(p);
            tr *= t[k];
        }

        // warp reductions
        #pragma unroll
        for (int off = 16; off > 0; off >>= 1) {
            c0  += __shfl_down_sync(0xffffffffu, c0,  off);
            c1  += __shfl_down_sync(0xffffffffu, c1,  off);
            c2  += __shfl_down_sync(0xffffffffu, c2,  off);
            dn  += __shfl_down_sync(0xffffffffu, dn,  off);
            ws  += __shfl_down_sync(0xffffffffu, ws,  off);
            ent += __shfl_down_sync(0xffffffffu, ent, off);
        }

        if (lane == 0) {
            out[(size_t)ray * 3 + 0] = c0;
            out[(size_t)ray * 3 + 1] = c1;
            out[(size_t)ray * 3 + 2] = c2;
            out[(size_t)3 * N + ray] = dn / (ws + 1e-5f);
            const float p_last = (1.0f - ws + 1e-6f) * invD;
            if (p_last > 0.0f) ent += p_last * __logf(p_last);
            sh_ent[warp] = ent;
        }
    } else if (lane == 0) {
        sh_ent[warp] = 0.0f;
    }

    __syncthreads();

    // ---- fused deterministic grid reduction (threadfence-reduction pattern) ----
    if (threadIdx.x == 0) {
        float s = 0.0f;
        #pragma unroll
        for (int w = 0; w < RPB; w++) s += sh_ent[w];
        g_partials[blockIdx.x] = s;
        __threadfence();
        const unsigned int done = atomicAdd(&g_count, 1u);
        sh_last = (done == gridDim.x - 1);
    }
    __syncthreads();

    if (sh_last) {
        // last block: sum all partials in a fixed order -> deterministic
        double s = 0.0;
        for (int i = threadIdx.x; i < (int)gridDim.x; i += 256)
            s += (double)g_partials[i];
        sh_red[threadIdx.x] = s;
        __syncthreads();
        #pragma unroll
        for (int off = 128; off > 0; off >>= 1) {
            if (threadIdx.x < off) sh_red[threadIdx.x] += sh_red[threadIdx.x + off];
            __syncthreads();
        }
        if (threadIdx.x == 0) {
            out[(size_t)4 * N] = (float)(-sh_red[0]);   // sparsity_loss
            g_count = 0;                                 // re-arm for next replay
        }
    }
}

extern "C" void kernel_launch(void* const* d_in, const int* in_sizes, int n_in,
                              void* d_out, int out_size)
{
    const float* raw    = (const float*)d_in[0];
    const float* zvals  = (const float*)d_in[1];
    const float* rays_d = (const float*)d_in[2];
    float* out = (float*)d_out;

    const int N = in_sizes[2] / 3;               // rays_d is [N,3]
    const int blocks = (N + RPB - 1) / RPB;

    integrate_kernel<<<blocks, 256>>>(raw, zvals, rays_d, out, N);
}

// round 5
// speedup vs baseline: 1.3177x; 1.0539x over previous
#include <cuda_runtime.h>
#include <math.h>

#define NEARV     2.0f
#define FARV      6.0f
#define FAR_DIST  1e10f
#define S         128
#define RPB       8            // rays per block (8 warps of 32 -> 256 threads)
#define MAX_BLK   16384
#define FULL      0xffffffffu

// Deterministic scratch for the fused scalar reduction (no allocations allowed).
__device__ float        g_partials[MAX_BLK];
__device__ unsigned int g_count = 0;

__global__ __launch_bounds__(256) void integrate_kernel(
    const float* __restrict__ raw,     // [N, S, 4]
    const float* __restrict__ zvals,   // [N, S]
    const float* __restrict__ rays_d,  // [N, 3]
    float* __restrict__ out,           // [3N chs | N depth | 1 scalar]
    int N)
{
    __shared__ float  sh_ent[RPB];
    __shared__ double sh_red[256];
    __shared__ bool   sh_last;

    const int warp = threadIdx.x >> 5;
    const int lane = threadIdx.x & 31;
    const int ray  = blockIdx.x * RPB + warp;

    float ent = 0.0f;
    if (ray < N) {
        // ---- fully coalesced loads: lane owns samples j = 32k + lane ----
        // raw: each request = 32 contiguous float4 = 512B (4 L1 lines)
        const float4* rp = (const float4*)raw + (size_t)ray * S;
        float4 r[4];
        #pragma unroll
        for (int k = 0; k < 4; k++) r[k] = rp[32 * k + lane];

        // zvals: 4 coalesced scalar loads (128B each)
        const float* zp = zvals + (size_t)ray * S;
        float z[4];
        #pragma unroll
        for (int k = 0; k < 4; k++) z[k] = zp[32 * k + lane];

        const float* rd = rays_d + (size_t)ray * 3;                // broadcast, L1
        const float nrm = sqrtf(rd[0] * rd[0] + rd[1] * rd[1] + rd[2] * rd[2]);

        // dists: z_{j+1} - z_j ; j+1 crosses slab boundary at lane 31
        float a[4], t[4];
        #pragma unroll
        for (int k = 0; k < 4; k++) {
            float znext = __shfl_down_sync(FULL, z[k], 1);
            // slab boundary: lane 31 of slab k needs lane 0 of slab k+1
            float zhead = (k < 3) ? __shfl_sync(FULL, z[(k + 1) & 3], 0) : 0.0f;
            float dist;
            if (lane == 31) dist = (k < 3) ? (zhead - z[k]) : FAR_DIST;
            else            dist = znext - z[k];
            dist *= nrm;
            const float alpha = 1.0f - __expf(-fmaxf(r[k].w, 0.0f) * dist);
            a[k] = alpha;
            t[k] = 1.0f - alpha + 1e-10f;
        }

        // per-slab inclusive multiplicative warp scans (independent -> ILP)
        float s0 = t[0], s1 = t[1], s2 = t[2], s3 = t[3];
        #pragma unroll
        for (int off = 1; off < 32; off <<= 1) {
            const float v0 = __shfl_up_sync(FULL, s0, off);
            const float v1 = __shfl_up_sync(FULL, s1, off);
            const float v2 = __shfl_up_sync(FULL, s2, off);
            const float v3 = __shfl_up_sync(FULL, s3, off);
            if (lane >= off) { s0 *= v0; s1 *= v1; s2 *= v2; s3 *= v3; }
        }
        float sc[4] = { s0, s1, s2, s3 };

        // exclusive scans + slab totals
        float excl[4], P[4];
        #pragma unroll
        for (int k = 0; k < 4; k++) {
            float e = __shfl_up_sync(FULL, sc[k], 1);
            excl[k] = (lane == 0) ? 1.0f : e;
            P[k]    = __shfl_sync(FULL, sc[k], 31);
        }

        // weights & accumulation
        const float invD = 1.0f / (1.0f + 1e-6f);
        float c0 = 0.f, c1 = 0.f, c2 = 0.f, dn = 0.f, ws = 0.f;
        float Ck = 1.0f;                     // cumulative product of prior slabs
        #pragma unroll
        for (int k = 0; k < 4; k++) {
            const float w = a[k] * Ck * excl[k];
            c0 += w * r[k].x;
            c1 += w * r[k].y;
            c2 += w * r[k].z;
            dn += w * (FARV - z[k]) * (1.0f / (FARV - NEARV));
            ws += w;
            const float p = w * invD;
            if (p > 0.0f) ent += p * __logf(p);
            Ck *= P[k];
        }

        // warp reductions
        #pragma unroll
        for (int off = 16; off > 0; off >>= 1) {
            c0  += __shfl_down_sync(FULL, c0,  off);
            c1  += __shfl_down_sync(FULL, c1,  off);
            c2  += __shfl_down_sync(FULL, c2,  off);
            dn  += __shfl_down_sync(FULL, dn,  off);
            ws  += __shfl_down_sync(FULL, ws,  off);
            ent += __shfl_down_sync(FULL, ent, off);
        }

        if (lane == 0) {
            out[(size_t)ray * 3 + 0] = c0;
            out[(size_t)ray * 3 + 1] = c1;
            out[(size_t)ray * 3 + 2] = c2;
            out[(size_t)3 * N + ray] = dn / (ws + 1e-5f);
            const float p_last = (1.0f - ws + 1e-6f) * invD;
            if (p_last > 0.0f) ent += p_last * __logf(p_last);
            sh_ent[warp] = ent;
        }
    } else if (lane == 0) {
        sh_ent[warp] = 0.0f;
    }

    __syncthreads();

    // ---- fused deterministic grid reduction (threadfence-reduction pattern) ----
    if (threadIdx.x == 0) {
        float s = 0.0f;
        #pragma unroll
        for (int w = 0; w < RPB; w++) s += sh_ent[w];
        g_partials[blockIdx.x] = s;
        __threadfence();
        const unsigned int done = atomicAdd(&g_count, 1u);
        sh_last = (done == gridDim.x - 1);
    }
    __syncthreads();

    if (sh_last) {
        double s = 0.0;
        for (int i = threadIdx.x; i < (int)gridDim.x; i += 256)
            s += (double)g_partials[i];
        sh_red[threadIdx.x] = s;
        __syncthreads();
        #pragma unroll
        for (int off = 128; off > 0; off >>= 1) {
            if (threadIdx.x < off) sh_red[threadIdx.x] += sh_red[threadIdx.x + off];
            __syncthreads();
        }
        if (threadIdx.x == 0) {
            out[(size_t)4 * N] = (float)(-sh_red[0]);   // sparsity_loss
            g_count = 0;                                 // re-arm for next replay
        }
    }
}

extern "C" void kernel_launch(void* const* d_in, const int* in_sizes, int n_in,
                              void* d_out, int out_size)
{
    const float* raw    = (const float*)d_in[0];
    const float* zvals  = (const float*)d_in[1];
    const float* rays_d = (const float*)d_in[2];
    float* out = (float*)d_out;

    const int N = in_sizes[2] / 3;               // rays_d is [N,3]
    const int blocks = (N + RPB - 1) / RPB;

    integrate_kernel<<<blocks, 256>>>(raw, zvals, rays_d, out, N);
}